// round 10
// baseline (speedup 1.0000x reference)
#include <cuda_runtime.h>
#include <cuda_bf16.h>

#define KDIM 256
#define TEMPF 1.0e8f
#define RPB 512          // rows per block (2 rows per thread in phase 1)
#define MAXC 8           // max window candidates per row

// Correctly-rounded (to ~2^-39 before final rounding) float exp for r in [-80, 0].
__device__ __forceinline__ float exp_cr(float r, const double* __restrict__ T)
{
    float nf = rintf(r * 46.166241f);                 // r * 32/ln2
    int n2 = (int)nf;
    int m  = n2 >> 5;
    int j  = n2 & 31;
    double fd = fma((double)nf, -2.1660849392498290e-2, (double)r);  // r - nf*ln2/32
    double p  = fma(fd, 1.0 / 24.0, 1.0 / 6.0);
    p = fma(fd, p, 0.5);
    p = fma(fd, p, 1.0);
    p = fma(fd, p, 1.0);
    float sf = (float)(T[j] * p);
    return sf * __int_as_float((m + 127) << 23);
}

struct RowOut {
    int   bk, nc;
    short kks[MAXC];
    float sv[MAXC];
    float qv;
};

__device__ __forceinline__ void process_row(
    float xv, const float* __restrict__ ssc, const short* __restrict__ sperm,
    const double* __restrict__ Texp, RowOut& o)
{
    // branchless lower_bound: lo = #elements < xv, in [0,256]
    int lo = 0;
#pragma unroll
    for (int s = 128; s; s >>= 1) {
        int m = lo + s;
        if (m <= KDIM && ssc[m - 1] < xv) lo = m;
    }

    const float aL = (lo > 0)    ? (xv - ssc[lo - 1]) : 3.0e38f;
    const float aR = (lo < KDIM) ? (ssc[lo] - xv)     : 3.0e38f;
    const float amin = fminf(aL, aR);

    // window: t = 1e8*(d - dmax) >= ~-24  <=>  a <= amin + ~2.2e-7/dmax
    const float d_est = __expf(-amin);
    const float wthr  = amin + 2.2e-7f / d_est;

    int   nc = 0;
    float avs[MAXC], cvs[MAXC];
    for (int p = lo - 1; p >= 0 && nc < MAXC; p--) {
        float a = xv - ssc[p];
        if (a > wthr) break;
        avs[nc] = a; cvs[nc] = ssc[p]; o.kks[nc] = sperm[p]; nc++;
    }
    for (int p = lo; p < KDIM && nc < MAXC; p++) {
        float a = ssc[p] - xv;
        if (a > wthr) break;
        avs[nc] = a; cvs[nc] = ssc[p]; o.kks[nc] = sperm[p]; nc++;
    }

    // accurate d on candidates; argmax with lowest-ORIGINAL-k tie-break
    float dcand[MAXC];
    float bd = -1.0f; int bk = 0;
    for (int i = 0; i < nc; i++) {
        float di = exp_cr(-avs[i], Texp);
        dcand[i] = di;
        int ki = o.kks[i];
        if (di > bd || (di == bd && ki < bk)) { bd = di; bk = ki; }
    }

    // softmax(TEMP*d): scale-then-subtract exactly like jax.nn.softmax
    const float amax = __fmul_rn(TEMPF, bd);
    float sum = 0.0f, qp = 0.0f;
    for (int i = 0; i < nc; i++) {
        float t = __fadd_rn(__fmul_rn(TEMPF, dcand[i]), -amax);
        float s = __expf(t);
        o.sv[i] = s;
        sum += s;
        qp  = __fmaf_rn(s, cvs[i], qp);
    }
    const float inv = 1.0f / sum;
    for (int i = 0; i < nc; i++) o.sv[i] *= inv;
    o.qv = qp * inv;
    o.bk = bk;
    o.nc = nc;
}

__global__ __launch_bounds__(256, 7) void quantizer_kernel(
    const float* __restrict__ x,      // (rows)
    const float* __restrict__ cb,     // (256)
    float* __restrict__ soft,         // (rows, 256)
    float* __restrict__ hard,         // (rows, 256)
    float* __restrict__ quant,        // (rows)
    int rows)
{
    __shared__ float  sraw[KDIM];               // codebook, natural order
    __shared__ float  ssc[KDIM];                // sorted values
    __shared__ short  sperm[KDIM];              // sorted pos -> original k
    __shared__ double Texp[32];
    __shared__ short  s_bk[RPB];
    __shared__ char   s_n [RPB];
    __shared__ short  s_idx[RPB][MAXC];
    __shared__ float  s_val[RPB][MAXC];

    const int tid  = threadIdx.x;
    const int row0 = blockIdx.x * RPB;
    const int rowA = row0 + tid;            // rows [row0, row0+256)
    const int rowB = rowA + 256;            // rows [row0+256, row0+512)

    // Issue x loads FIRST so they overlap the block-local sort below.
    const float xvA = (rowA < rows) ? x[rowA] : 0.0f;
    const float xvB = (rowB < rows) ? x[rowB] : 0.0f;

    // Block-local rank sort of the codebook (amortized over 512 rows).
    const float my = cb[tid];
    sraw[tid] = my;
    if (tid < 32) Texp[tid] = exp2((double)tid * 0.03125);
    __syncthreads();
    {
        int rank = 0;
        const float4* p4 = reinterpret_cast<const float4*>(sraw);
#pragma unroll 8
        for (int i = 0; i < 64; i++) {
            float4 c = p4[i];
            int j = 4 * i;
            rank += (c.x < my) || (c.x == my && (j + 0) < tid);
            rank += (c.y < my) || (c.y == my && (j + 1) < tid);
            rank += (c.z < my) || (c.z == my && (j + 2) < tid);
            rank += (c.w < my) || (c.w == my && (j + 3) < tid);
        }
        ssc[rank]   = my;
        sperm[rank] = (short)tid;
    }
    __syncthreads();

    // ---------------- Phase 1: two rows per thread ----------------
    RowOut oA, oB;
    if (rowA < rows) {
        process_row(xvA, ssc, sperm, Texp, oA);
        __stcs(quant + rowA, oA.qv);
        s_bk[tid] = (short)oA.bk;
        s_n [tid] = (char)oA.nc;
        for (int i = 0; i < oA.nc; i++) { s_idx[tid][i] = oA.kks[i]; s_val[tid][i] = oA.sv[i]; }
    } else { s_n[tid] = 0; s_bk[tid] = -1; }

    if (rowB < rows) {
        process_row(xvB, ssc, sperm, Texp, oB);
        __stcs(quant + rowB, oB.qv);
        s_bk[tid + 256] = (short)oB.bk;
        s_n [tid + 256] = (char)oB.nc;
        for (int i = 0; i < oB.nc; i++) { s_idx[tid + 256][i] = oB.kks[i]; s_val[tid + 256][i] = oB.sv[i]; }
    } else { s_n[tid + 256] = 0; s_bk[tid + 256] = -1; }
    __syncthreads();

    // ---------------- Phase 2: warp-per-row dense streaming stores ----------------
    const int lane = tid & 31;
    const int warp = tid >> 5;
    const int k0 = 4 * lane;          // entries k0..k0+3
    const int k1 = 128 + 4 * lane;    // entries k1..k1+3

    for (int rr = warp; rr < RPB; rr += 8) {
        const int grow = row0 + rr;
        if (grow >= rows) break;
        const int n  = s_n[rr];
        const int bk = s_bk[rr];
        const size_t base = (size_t)grow * KDIM;

        float4 sv0 = make_float4(0.f, 0.f, 0.f, 0.f);
        float4 sv1 = make_float4(0.f, 0.f, 0.f, 0.f);
        for (int i = 0; i < n; i++) {
            const int   ki = s_idx[rr][i];     // LDS broadcast
            const float vi = s_val[rr][i];
            sv0.x = (ki == k0    ) ? vi : sv0.x;
            sv0.y = (ki == k0 + 1) ? vi : sv0.y;
            sv0.z = (ki == k0 + 2) ? vi : sv0.z;
            sv0.w = (ki == k0 + 3) ? vi : sv0.w;
            sv1.x = (ki == k1    ) ? vi : sv1.x;
            sv1.y = (ki == k1 + 1) ? vi : sv1.y;
            sv1.z = (ki == k1 + 2) ? vi : sv1.z;
            sv1.w = (ki == k1 + 3) ? vi : sv1.w;
        }
        float4 hv0 = make_float4(bk == k0     ? 1.f : 0.f,
                                 bk == k0 + 1 ? 1.f : 0.f,
                                 bk == k0 + 2 ? 1.f : 0.f,
                                 bk == k0 + 3 ? 1.f : 0.f);
        float4 hv1 = make_float4(bk == k1     ? 1.f : 0.f,
                                 bk == k1 + 1 ? 1.f : 0.f,
                                 bk == k1 + 2 ? 1.f : 0.f,
                                 bk == k1 + 3 ? 1.f : 0.f);

        // Streaming (evict-first) stores: output is write-once, never re-read.
        __stcs(reinterpret_cast<float4*>(soft + base) + lane,       sv0);
        __stcs(reinterpret_cast<float4*>(soft + base + 128) + lane, sv1);
        __stcs(reinterpret_cast<float4*>(hard + base) + lane,       hv0);
        __stcs(reinterpret_cast<float4*>(hard + base + 128) + lane, hv1);
    }
}

extern "C" void kernel_launch(void* const* d_in, const int* in_sizes, int n_in,
                              void* d_out, int out_size)
{
    const float* x  = (const float*)d_in[0];   // inputs (1024,512) f32
    const float* cb = (const float*)d_in[1];   // codebook (1,256) f32
    const int rows  = in_sizes[0];             // 524288

    float* out   = (float*)d_out;              // [soft | hard | quantized]
    float* soft  = out;
    float* hard  = out + (size_t)rows * KDIM;
    float* quant = out + 2ull * (size_t)rows * KDIM;

    const int blocks = (rows + RPB - 1) / RPB;
    quantizer_kernel<<<blocks, 256>>>(x, cb, soft, hard, quant, rows);
}

// round 11
// speedup vs baseline: 1.0965x; 1.0965x over previous
#include <cuda_runtime.h>
#include <cuda_bf16.h>

#define KDIM 256
#define TEMPF 1.0e8f
#define RPB 256          // rows per block (1 thread per row in phase 1)
#define MAXC 8           // max window candidates per row
#define NB 64            // value buckets over [-1/256, 1/256]
#define B0 (-0.00390625f)            // -1/256
#define BW (1.220703125e-4f)         // (2/256)/64

__device__ __forceinline__ int bucket_of(float v)
{
    int b = (int)((v - B0) * 8192.0f);   // 1/BW = 8192
    return min(NB - 1, max(0, b));
}

// Correctly-rounded (to ~2^-39 before final rounding) float exp for r in [-80, 0].
__device__ __forceinline__ float exp_cr(float r, const double* __restrict__ T)
{
    float nf = rintf(r * 46.166241f);                 // r * 32/ln2
    int n2 = (int)nf;
    int m  = n2 >> 5;
    int j  = n2 & 31;
    double fd = fma((double)nf, -2.1660849392498290e-2, (double)r);  // r - nf*ln2/32
    double p  = fma(fd, 1.0 / 24.0, 1.0 / 6.0);
    p = fma(fd, p, 0.5);
    p = fma(fd, p, 1.0);
    p = fma(fd, p, 1.0);
    float sf = (float)(T[j] * p);
    return sf * __int_as_float((m + 127) << 23);
}

__global__ __launch_bounds__(256, 8) void quantizer_kernel(
    const float* __restrict__ x,      // (rows)
    const float* __restrict__ cb,     // (256)
    float* __restrict__ soft,         // (rows, 256)
    float* __restrict__ hard,         // (rows, 256)
    float* __restrict__ quant,        // (rows)
    int rows)
{
    __shared__ int    scnt[NB];
    __shared__ int    sstart[NB + 1];
    __shared__ int    scur[NB];
    __shared__ float  bval[KDIM];               // bucket-grouped values
    __shared__ short  bkk [KDIM];               // bucket-grouped original k
    __shared__ double Texp[32];
    __shared__ short  s_bk[RPB];
    __shared__ char   s_n [RPB];
    __shared__ short  s_idx[RPB][MAXC];
    __shared__ float  s_val[RPB][MAXC];

    const int tid  = threadIdx.x;
    const int row0 = blockIdx.x * RPB;
    const int row  = row0 + tid;

    // Issue x load first so it overlaps the bucket build.
    const float xv = (row < rows) ? x[row] : 0.0f;
    const float cv_own = cb[tid];

    if (tid < NB) scnt[tid] = 0;
    if (tid < 32) Texp[tid] = exp2((double)tid * 0.03125);
    __syncthreads();

    const int myb = bucket_of(cv_own);
    atomicAdd(&scnt[myb], 1);
    __syncthreads();

    // Exclusive scan over 64 counts, warp 0 only (2 elems/lane, shfl scan).
    if (tid < 32) {
        int c0 = scnt[tid], c1 = scnt[tid + 32];
        int p0 = c0, p1 = c1;
#pragma unroll
        for (int off = 1; off < 32; off <<= 1) {
            int t0 = __shfl_up_sync(0xFFFFFFFFu, p0, off);
            int t1 = __shfl_up_sync(0xFFFFFFFFu, p1, off);
            if ((tid & 31) >= off) { p0 += t0; p1 += t1; }
        }
        int tot0 = __shfl_sync(0xFFFFFFFFu, p0, 31);   // sum of first 32 buckets
        sstart[tid]      = p0 - c0;                    // exclusive
        sstart[tid + 32] = tot0 + p1 - c1;
        scur[tid]        = p0 - c0;
        scur[tid + 32]   = tot0 + p1 - c1;
        if (tid == 31) sstart[NB] = KDIM;
    }
    __syncthreads();

    {   // scatter (order within bucket nondeterministic -> fixed by k-sort later)
        int pos = atomicAdd(&scur[myb], 1);
        bval[pos] = cv_own;
        bkk [pos] = (short)tid;
    }
    __syncthreads();

    // ---------------- Phase 1: thread-per-row sparse compute ----------------
    if (row < rows) {
        // nearest-neighbor via expanding bucket scan
        const int bx = bucket_of(xv);
        float best = 3.0e38f;
        for (int p = sstart[bx]; p < sstart[bx + 1]; p++)
            best = fminf(best, fabsf(xv - bval[p]));
        int l = bx - 1, r = bx + 1;
        while (true) {
            float dl = (l >= 0) ? (xv - (B0 + (float)(l + 1) * BW)) : 3.0e38f;
            float dr = (r < NB) ? ((B0 + (float)r * BW) - xv)       : 3.0e38f;
            if (dl <= dr) {
                if (dl > best + 4e-9f) break;          // fuzz-padded prune
                for (int p = sstart[l]; p < sstart[l + 1]; p++)
                    best = fminf(best, fabsf(xv - bval[p]));
                l--;
            } else {
                if (dr > best + 4e-9f) break;
                for (int p = sstart[r]; p < sstart[r + 1]; p++)
                    best = fminf(best, fabsf(xv - bval[p]));
                r++;
            }
        }
        const float amin = best;

        // window: t = 1e8*(d - dmax) >= ~-24  <=>  a <= amin + ~2.2e-7/dmax
        const float d_est = __expf(-amin);
        const float wthr  = amin + 2.2e-7f / d_est;

        // collect candidates from buckets overlapping [xv-wthr, xv+wthr]
        int   nc = 0;
        float avs[MAXC], cvs[MAXC];
        short kks[MAXC];
        const int bL = bucket_of(xv - wthr - 1e-8f);
        const int bR = bucket_of(xv + wthr + 1e-8f);
        for (int b = bL; b <= bR; b++)
            for (int p = sstart[b]; p < sstart[b + 1]; p++) {
                float cv = bval[p];
                float a  = fabsf(xv - cv);
                if (a <= wthr && nc < MAXC) {
                    avs[nc] = a; cvs[nc] = cv; kks[nc] = bkk[p]; nc++;
                }
            }

        // sort candidates by original k (nc <= 8; deterministic sum order)
        for (int i = 1; i < nc; i++) {
            short ki = kks[i]; float ai = avs[i], ci = cvs[i];
            int j = i - 1;
            while (j >= 0 && kks[j] > ki) {
                kks[j + 1] = kks[j]; avs[j + 1] = avs[j]; cvs[j + 1] = cvs[j];
                j--;
            }
            kks[j + 1] = ki; avs[j + 1] = ai; cvs[j + 1] = ci;
        }

        // accurate d on candidates; argmax with lowest-ORIGINAL-k tie-break
        float dcand[MAXC];
        float bd = -1.0f; int bk = 0;
        for (int i = 0; i < nc; i++) {
            float di = exp_cr(-avs[i], Texp);
            dcand[i] = di;
            int ki = kks[i];
            if (di > bd || (di == bd && ki < bk)) { bd = di; bk = ki; }
        }

        // softmax(TEMP*d): scale-then-subtract exactly like jax.nn.softmax
        const float amax = __fmul_rn(TEMPF, bd);
        float sum = 0.0f, qp = 0.0f;
        float sv[MAXC];
        for (int i = 0; i < nc; i++) {
            float t = __fadd_rn(__fmul_rn(TEMPF, dcand[i]), -amax);
            float s = __expf(t);
            sv[i] = s;
            sum += s;
            qp  = __fmaf_rn(s, cvs[i], qp);
        }
        const float inv = 1.0f / sum;
        __stcs(quant + row, qp * inv);

        s_bk[tid] = (short)bk;
        s_n [tid] = (char)nc;
        for (int i = 0; i < nc; i++) {
            s_idx[tid][i] = kks[i];
            s_val[tid][i] = sv[i] * inv;
        }
    } else {
        s_n[tid] = 0; s_bk[tid] = -1;
    }
    __syncthreads();

    // ---------------- Phase 2: warp-per-row dense streaming stores ----------------
    const int lane = tid & 31;
    const int warp = tid >> 5;
    const int k0 = 4 * lane;          // entries k0..k0+3
    const int k1 = 128 + 4 * lane;    // entries k1..k1+3

    for (int rr = warp; rr < RPB; rr += 8) {
        const int grow = row0 + rr;
        if (grow >= rows) break;
        const int n  = s_n[rr];
        const int bk = s_bk[rr];
        const size_t base = (size_t)grow * KDIM;

        float4 sv0 = make_float4(0.f, 0.f, 0.f, 0.f);
        float4 sv1 = make_float4(0.f, 0.f, 0.f, 0.f);
        for (int i = 0; i < n; i++) {
            const int   ki = s_idx[rr][i];     // LDS broadcast
            const float vi = s_val[rr][i];
            sv0.x = (ki == k0    ) ? vi : sv0.x;
            sv0.y = (ki == k0 + 1) ? vi : sv0.y;
            sv0.z = (ki == k0 + 2) ? vi : sv0.z;
            sv0.w = (ki == k0 + 3) ? vi : sv0.w;
            sv1.x = (ki == k1    ) ? vi : sv1.x;
            sv1.y = (ki == k1 + 1) ? vi : sv1.y;
            sv1.z = (ki == k1 + 2) ? vi : sv1.z;
            sv1.w = (ki == k1 + 3) ? vi : sv1.w;
        }
        float4 hv0 = make_float4(bk == k0     ? 1.f : 0.f,
                                 bk == k0 + 1 ? 1.f : 0.f,
                                 bk == k0 + 2 ? 1.f : 0.f,
                                 bk == k0 + 3 ? 1.f : 0.f);
        float4 hv1 = make_float4(bk == k1     ? 1.f : 0.f,
                                 bk == k1 + 1 ? 1.f : 0.f,
                                 bk == k1 + 2 ? 1.f : 0.f,
                                 bk == k1 + 3 ? 1.f : 0.f);

        // Streaming (evict-first) stores: output is write-once, never re-read.
        __stcs(reinterpret_cast<float4*>(soft + base) + lane,       sv0);
        __stcs(reinterpret_cast<float4*>(soft + base + 128) + lane, sv1);
        __stcs(reinterpret_cast<float4*>(hard + base) + lane,       hv0);
        __stcs(reinterpret_cast<float4*>(hard + base + 128) + lane, hv1);
    }
}

extern "C" void kernel_launch(void* const* d_in, const int* in_sizes, int n_in,
                              void* d_out, int out_size)
{
    const float* x  = (const float*)d_in[0];   // inputs (1024,512) f32
    const float* cb = (const float*)d_in[1];   // codebook (1,256) f32
    const int rows  = in_sizes[0];             // 524288

    float* out   = (float*)d_out;              // [soft | hard | quantized]
    float* soft  = out;
    float* hard  = out + (size_t)rows * KDIM;
    float* quant = out + 2ull * (size_t)rows * KDIM;

    const int blocks = (rows + RPB - 1) / RPB;
    quantizer_kernel<<<blocks, 256>>>(x, cb, soft, hard, quant, rows);
}